// round 11
// baseline (speedup 1.0000x reference)
#include <cuda_runtime.h>
#include <cuda_fp16.h>
#include <math.h>
#include <stdint.h>

#define T_TOK 4096
#define DIM   1024
#define HID   4096
#define NE    8

#define BM 128
#define BN 128
#define MAX_SLOTS 9216        // 8192 pairs + worst-case per-expert padding, 72 tiles
#define MTILES (MAX_SLOTS/BM)

#define ASTG 10240            // 128 rows * 80 B
#define BSTG 8704             // 32 rows * 272 B
#define NST  3
#define GEMM_SMEM (NST*(ASTG+BSTG))   // 56832 -> 2 CTAs/SM

// ---------------- device scratch (static) ----------------
__device__ int   g_off[NE];
__device__ int   g_cursor[NE];
__device__ int   g_padded_total;
__device__ int   g_sel[T_TOK][2];
__device__ float g_wts[T_TOK][2];
__device__ int   g_slot_tok[MAX_SLOTS];
__device__ int   g_slot_e[MAX_SLOTS];
__device__ float g_slot_w[MAX_SLOTS];
__device__ int   g_tok_slot[T_TOK][2];

__device__ __align__(256) __half g_Xf[T_TOK * DIM];                 // token-major fp16
__device__ __align__(256) __half g_W1f[(size_t)NE * DIM * HID];
__device__ __align__(256) __half g_W2f[(size_t)NE * HID * DIM];
__device__ __align__(256) __half g_Hf[(size_t)MAX_SLOTS * HID];     // slot-major fp16
__device__ __align__(256) __half g_Y[(size_t)MAX_SLOTS * DIM];      // fp16 expert outputs

// ---------------- helpers ----------------
__device__ __forceinline__ uint32_t smem_u32(const void* p) {
    uint32_t a;
    asm("{ .reg .u64 t; cvta.to.shared.u64 t, %1; cvt.u32.u64 %0, t; }" : "=r"(a) : "l"(p));
    return a;
}
__device__ __forceinline__ void cp16(uint32_t dst, const void* src) {
    asm volatile("cp.async.cg.shared.global [%0], [%1], 16;" :: "r"(dst), "l"(src) : "memory");
}
__device__ __forceinline__ void ldm_x4(uint32_t* r, uint32_t addr) {
    asm volatile("ldmatrix.sync.aligned.m8n8.x4.shared.b16 {%0,%1,%2,%3}, [%4];"
                 : "=r"(r[0]), "=r"(r[1]), "=r"(r[2]), "=r"(r[3]) : "r"(addr));
}
__device__ __forceinline__ void ldm_x4_t(uint32_t* r, uint32_t addr) {
    asm volatile("ldmatrix.sync.aligned.m8n8.x4.trans.shared.b16 {%0,%1,%2,%3}, [%4];"
                 : "=r"(r[0]), "=r"(r[1]), "=r"(r[2]), "=r"(r[3]) : "r"(addr));
}
__device__ __forceinline__ void mma16816(float* d, const uint32_t* a, uint32_t b0, uint32_t b1) {
    asm volatile("mma.sync.aligned.m16n8k16.row.col.f32.f16.f16.f32 "
                 "{%0,%1,%2,%3}, {%4,%5,%6,%7}, {%8,%9}, {%0,%1,%2,%3};"
                 : "+f"(d[0]), "+f"(d[1]), "+f"(d[2]), "+f"(d[3])
                 : "r"(a[0]), "r"(a[1]), "r"(a[2]), "r"(a[3]), "r"(b0), "r"(b1));
}

// ---------------- prep kernels ----------------
// 256 threads = 8 tokens/block; Wr staged transposed in smem, x read as coalesced float4
__global__ __launch_bounds__(256) void route_kernel(const float* __restrict__ x,
                                                    const float* __restrict__ Wr,
                                                    const float* __restrict__ br) {
    __shared__ float sW[NE][DIM];       // 32 KB
    __shared__ float sb[NE];
    const int tid = threadIdx.x;

    const float4* Wr4 = (const float4*)Wr;
#pragma unroll
    for (int c = 0; c < 8; c++) {
        int idx = tid + 256 * c;        // 0..2047 float4s = [k][e] pairs
        float4 f = Wr4[idx];
        int k = idx >> 1, e0 = (idx & 1) * 4;
        sW[e0][k] = f.x; sW[e0 + 1][k] = f.y; sW[e0 + 2][k] = f.z; sW[e0 + 3][k] = f.w;
    }
    if (tid < NE) sb[tid] = br[tid];
    __syncthreads();

    const int warp = tid >> 5, lane = tid & 31;
    const int token = blockIdx.x * 8 + warp;
    const float* xr = x + (size_t)token * DIM;

    float acc[NE];
#pragma unroll
    for (int e = 0; e < NE; e++) acc[e] = 0.0f;
#pragma unroll
    for (int i = 0; i < 8; i++) {
        int k = 4 * lane + 128 * i;
        float4 xv = *(const float4*)(xr + k);
#pragma unroll
        for (int e = 0; e < NE; e++) {
            float4 w = *(const float4*)(&sW[e][k]);
            acc[e] += xv.x * w.x + xv.y * w.y + xv.z * w.z + xv.w * w.w;
        }
    }
#pragma unroll
    for (int e = 0; e < NE; e++)
#pragma unroll
        for (int o = 16; o > 0; o >>= 1)
            acc[e] += __shfl_down_sync(0xFFFFFFFFu, acc[e], o);

    if (lane == 0) {
        float l[NE];
#pragma unroll
        for (int e = 0; e < NE; e++) l[e] = acc[e] + sb[e];
        int i0 = 0;
#pragma unroll
        for (int e = 1; e < NE; e++) if (l[e] > l[i0]) i0 = e;
        int i1 = (i0 == 0) ? 1 : 0;
#pragma unroll
        for (int e = 0; e < NE; e++) if (e != i0 && l[e] > l[i1]) i1 = e;
        float w0 = 1.0f / (1.0f + expf(l[i1] - l[i0]));
        g_sel[token][0] = i0; g_sel[token][1] = i1;
        g_wts[token][0] = w0; g_wts[token][1] = 1.0f - w0;
    }
}

// single block: count experts from g_sel, compute padded offsets, init slots & cursors
__global__ __launch_bounds__(1024) void offsets_kernel() {
    __shared__ int wcnt[32][NE];
    __shared__ int soff[NE + 1];
    const int tid = threadIdx.x, wp = tid >> 5, ln = tid & 31;
    if (ln < NE) wcnt[wp][ln] = 0;
    __syncthreads();
    for (int t = tid; t < T_TOK; t += 1024) {
        atomicAdd(&wcnt[wp][g_sel[t][0]], 1);
        atomicAdd(&wcnt[wp][g_sel[t][1]], 1);
    }
    __syncthreads();
    if (tid == 0) {
        int tot = 0;
        for (int e = 0; e < NE; e++) {
            int c = 0;
            for (int w = 0; w < 32; w++) c += wcnt[w][e];
            g_off[e] = tot; soff[e] = tot;
            g_cursor[e] = 0;
            tot += ((c + BM - 1) / BM) * BM;
        }
        soff[NE] = tot;
        g_padded_total = tot;
    }
    __syncthreads();
    int tot = soff[NE];
    for (int s = tid; s < tot; s += 1024) {
        int e = 0;
        while (s >= soff[e + 1]) e++;
        g_slot_e[s] = e;
        g_slot_tok[s] = -1;
    }
}

__global__ void scatter_kernel() {
    int t = blockIdx.x * blockDim.x + threadIdx.x;
    if (t >= T_TOK) return;
#pragma unroll
    for (int j = 0; j < 2; j++) {
        int e = g_sel[t][j];
        int pos = atomicAdd(&g_cursor[e], 1);
        int s = g_off[e] + pos;
        g_slot_tok[s] = t;
        g_slot_w[s] = g_wts[t][j];
        g_tok_slot[t][j] = s;
    }
}

// X fp32 token-major -> fp16 token-major (GEMM1 gathers rows directly)
__global__ void convertX_kernel(const float* __restrict__ x) {
    int idx = blockIdx.x * blockDim.x + threadIdx.x;
    if (idx >= T_TOK * DIM / 4) return;
    float4 v = *(const float4*)(x + (size_t)idx * 4);
    *(__half2*)(g_Xf + (size_t)idx * 4)     = __floats2half2_rn(v.x, v.y);
    *(__half2*)(g_Xf + (size_t)idx * 4 + 2) = __floats2half2_rn(v.z, v.w);
}

__global__ void convert_f16_kernel(const float* __restrict__ src,
                                   __half* __restrict__ dst, size_t n4) {
    size_t idx = blockIdx.x * (size_t)blockDim.x + threadIdx.x;
    size_t stride = (size_t)gridDim.x * blockDim.x;
    for (size_t i = idx; i < n4; i += stride) {
        float4 v = *(const float4*)(src + i * 4);
        *(__half2*)(dst + i * 4)     = __floats2half2_rn(v.x, v.y);
        *(__half2*)(dst + i * 4 + 2) = __floats2half2_rn(v.z, v.w);
    }
}

// convert columns [c0, c0+HID/2) of the [NE*DIM, HID] W1 matrix
__global__ void convert_cols_kernel(const float* __restrict__ src,
                                    __half* __restrict__ dst, int c0) {
    const int perrow = (HID / 2) / 4;    // 512 float4s per row half
    int idx = blockIdx.x * blockDim.x + threadIdx.x;
    if (idx >= NE * DIM * perrow) return;
    int row = idx / perrow;
    int col = c0 + (idx - row * perrow) * 4;
    size_t o = (size_t)row * HID + col;
    float4 v = *(const float4*)(src + o);
    *(__half2*)(dst + o)     = __floats2half2_rn(v.x, v.y);
    *(__half2*)(dst + o + 2) = __floats2half2_rn(v.z, v.w);
}

// ---------------- HMMA GEMM: C[128x128] = A[m,k] * B[k,n], fp16 in / fp32 acc ----------------
// 8 warps, warp grid 4m x 2n, warp tile 32x64. 3-stage cp.async, BK=32, one sync/iter.
// MODE 0: A gathered from token-major g_Xf via slot_tok; +b1, exact GELU -> g_Hf.
// MODE 1: A = g_Hf slot-major; +b2 -> g_Y (fp16).
template<int KD, int NSZ, int MODE>
__global__ __launch_bounds__(256, 2) void gemm_mma_kernel(const __half* __restrict__ A,
                                                          const __half* __restrict__ Bw,
                                                          const float* __restrict__ bias,
                                                          int n_base) {
    extern __shared__ char smem[];
    const int m0 = blockIdx.x * BM;
    if (m0 >= g_padded_total) return;
    const int n0 = (blockIdx.y + n_base) * BN;
    const int e  = g_slot_e[m0];
    const __half* B = Bw + (size_t)e * KD * NSZ;

    const int tid = threadIdx.x, wid = tid >> 5, lane = tid & 31;
    const int wm = wid >> 1, wn = wid & 1;
    const uint32_t asb = smem_u32(smem);
    const uint32_t bsb = asb + NST * ASTG;
    constexpr int NT = KD / 32;

    // per-thread load coords (A: 2 x 16B, B: 2 x 16B per thread per stage)
    const int ar  = tid >> 2,         akc  = tid & 3;
    const int ar2 = (tid + 256) >> 2, akc2 = (tid + 256) & 3;
    const int br_ = tid >> 4,         bnc  = tid & 15;
    const int br2 = (tid + 256) >> 4, bnc2 = (tid + 256) & 15;

    // A source row pointers, computed once (MODE 0 gathers via slot_tok)
    const __half *ap0, *ap1;
    if (MODE == 0) {
        int t0 = g_slot_tok[m0 + ar];  if (t0 < 0) t0 = 0;
        int t1 = g_slot_tok[m0 + ar2]; if (t1 < 0) t1 = 0;
        ap0 = A + (size_t)t0 * KD + akc  * 8;
        ap1 = A + (size_t)t1 * KD + akc2 * 8;
    } else {
        ap0 = A + (size_t)(m0 + ar ) * KD + akc  * 8;
        ap1 = A + (size_t)(m0 + ar2) * KD + akc2 * 8;
    }

    float acc[2][8][4];
#pragma unroll
    for (int i = 0; i < 2; i++)
#pragma unroll
        for (int j = 0; j < 8; j++)
#pragma unroll
            for (int q = 0; q < 4; q++) acc[i][j][q] = 0.0f;

#define LOAD_STAGE(KT, BUF) do {                                                           \
    uint32_t ab = asb + (BUF) * ASTG;                                                      \
    uint32_t bb = bsb + (BUF) * BSTG;                                                      \
    cp16(ab + ar  * 80 + akc  * 16, ap0 + (KT) * 32);                                      \
    cp16(ab + ar2 * 80 + akc2 * 16, ap1 + (KT) * 32);                                      \
    cp16(bb + br_ * 272 + bnc  * 16, B + (size_t)((KT) * 32 + br_) * NSZ + n0 + bnc  * 8); \
    cp16(bb + br2 * 272 + bnc2 * 16, B + (size_t)((KT) * 32 + br2) * NSZ + n0 + bnc2 * 8); \
} while (0)

    // prologue: prefetch 2 stages
    LOAD_STAGE(0, 0);
    asm volatile("cp.async.commit_group;" ::: "memory");
    LOAD_STAGE(1, 1);
    asm volatile("cp.async.commit_group;" ::: "memory");

    // ldmatrix base offsets (constant per thread; mapping verified round-3/5)
    const uint32_t a_row_off = (uint32_t)((wm * 32 + (lane & 15)) * 80 + (lane >> 4) * 16);
    const uint32_t b_off = (uint32_t)(((lane & 7) + ((lane >> 3) & 1) * 8) * 272
                                      + (wn * 64 + (lane >> 4) * 8) * 2);

    int cbuf = 0, lbuf = 2;     // compute buffer, load buffer
#pragma unroll 1
    for (int kt = 0; kt < NT; kt++) {
        asm volatile("cp.async.wait_group 1;" ::: "memory");
        __syncthreads();

        if (kt + 2 < NT) LOAD_STAGE(kt + 2, lbuf);
        asm volatile("cp.async.commit_group;" ::: "memory");
        if (++lbuf == NST) lbuf = 0;

        uint32_t ab = asb + cbuf * ASTG;
        uint32_t bb = bsb + cbuf * BSTG;
        if (++cbuf == NST) cbuf = 0;
#pragma unroll
        for (int k16 = 0; k16 < 2; k16++) {
            uint32_t a[2][4];
            ldm_x4(a[0], ab + a_row_off + k16 * 32);
            ldm_x4(a[1], ab + a_row_off + 16 * 80 + k16 * 32);
            uint32_t b[4][4];
#pragma unroll
            for (int p = 0; p < 4; p++)
                ldm_x4_t(b[p], bb + b_off + k16 * 16 * 272 + p * 32);
#pragma unroll
            for (int mt = 0; mt < 2; mt++)
#pragma unroll
                for (int p = 0; p < 4; p++) {
                    mma16816(acc[mt][2 * p],     a[mt], b[p][0], b[p][1]);
                    mma16816(acc[mt][2 * p + 1], a[mt], b[p][2], b[p][3]);
                }
        }
    }
#undef LOAD_STAGE

    // epilogue
    const int group = lane >> 2, tig = lane & 3;
#pragma unroll
    for (int mt = 0; mt < 2; mt++) {
        int r = m0 + wm * 32 + mt * 16 + group;
#pragma unroll
        for (int nt = 0; nt < 8; nt++) {
            int c = n0 + wn * 64 + nt * 8 + tig * 2;
            float b0 = __ldg(bias + (size_t)e * NSZ + c);
            float b1v = __ldg(bias + (size_t)e * NSZ + c + 1);
            float v0 = acc[mt][nt][0] + b0;
            float v1 = acc[mt][nt][1] + b1v;
            float v2 = acc[mt][nt][2] + b0;
            float v3 = acc[mt][nt][3] + b1v;
            if (MODE == 0) {
                v0 = 0.5f * v0 * (1.0f + erff(v0 * 0.70710678118654752f));
                v1 = 0.5f * v1 * (1.0f + erff(v1 * 0.70710678118654752f));
                v2 = 0.5f * v2 * (1.0f + erff(v2 * 0.70710678118654752f));
                v3 = 0.5f * v3 * (1.0f + erff(v3 * 0.70710678118654752f));
                *(__half2*)(g_Hf + (size_t)r * NSZ + c)       = __floats2half2_rn(v0, v1);
                *(__half2*)(g_Hf + (size_t)(r + 8) * NSZ + c) = __floats2half2_rn(v2, v3);
            } else {
                *(__half2*)(g_Y + (size_t)r * NSZ + c)       = __floats2half2_rn(v0, v1);
                *(__half2*)(g_Y + (size_t)(r + 8) * NSZ + c) = __floats2half2_rn(v2, v3);
            }
        }
    }
}

// ---------------- weighted combine (fp16 Y -> fp32 out) ----------------
__global__ void combine_kernel(float* __restrict__ out) {
    int idx = blockIdx.x * blockDim.x + threadIdx.x;
    if (idx >= T_TOK * DIM / 4) return;
    int t = idx >> 8;
    int c = (idx & 255) << 2;
    int s0 = g_tok_slot[t][0], s1 = g_tok_slot[t][1];
    float w0 = g_slot_w[s0], w1 = g_slot_w[s1];
    const __half2* a2 = (const __half2*)(g_Y + (size_t)s0 * DIM + c);
    const __half2* b2 = (const __half2*)(g_Y + (size_t)s1 * DIM + c);
    float2 a01 = __half22float2(a2[0]), a23 = __half22float2(a2[1]);
    float2 b01 = __half22float2(b2[0]), b23 = __half22float2(b2[1]);
    float4 o;
    o.x = w0 * a01.x + w1 * b01.x;
    o.y = w0 * a01.y + w1 * b01.y;
    o.z = w0 * a23.x + w1 * b23.x;
    o.w = w0 * a23.y + w1 * b23.y;
    *(float4*)(out + (size_t)t * DIM + c) = o;
}

// ---------------- host ----------------
extern "C" void kernel_launch(void* const* d_in, const int* in_sizes, int n_in,
                              void* d_out, int out_size) {
    const float* x  = (const float*)d_in[0];
    const float* Wr = (const float*)d_in[1];
    const float* br = (const float*)d_in[2];
    const float* W1 = (const float*)d_in[3];
    const float* b1 = (const float*)d_in[4];
    const float* W2 = (const float*)d_in[5];
    const float* b2 = (const float*)d_in[6];
    float* out = (float*)d_out;

    void* pW1f; cudaGetSymbolAddress(&pW1f, g_W1f);
    void* pW2f; cudaGetSymbolAddress(&pW2f, g_W2f);
    void* pXf;  cudaGetSymbolAddress(&pXf,  g_Xf);
    void* pHf;  cudaGetSymbolAddress(&pHf,  g_Hf);

    cudaFuncSetAttribute(gemm_mma_kernel<DIM, HID, 0>, cudaFuncAttributeMaxDynamicSharedMemorySize, GEMM_SMEM);
    cudaFuncSetAttribute(gemm_mma_kernel<HID, DIM, 1>, cudaFuncAttributeMaxDynamicSharedMemorySize, GEMM_SMEM);

    // side streams forked off the capturing (legacy) stream
    cudaStream_t side, side2;
    cudaStreamCreateWithFlags(&side,  cudaStreamNonBlocking);
    cudaStreamCreateWithFlags(&side2, cudaStreamNonBlocking);
    cudaEvent_t evFork, evW1a, evW1b, evW2, evX;
    cudaEventCreateWithFlags(&evFork, cudaEventDisableTiming);
    cudaEventCreateWithFlags(&evW1a,  cudaEventDisableTiming);
    cudaEventCreateWithFlags(&evW1b,  cudaEventDisableTiming);
    cudaEventCreateWithFlags(&evW2,   cudaEventDisableTiming);
    cudaEventCreateWithFlags(&evX,    cudaEventDisableTiming);

    size_t wn4 = (size_t)NE * DIM * HID / 4;
    const int colsGrid = (NE * DIM * (HID / 2) / 4 + 255) / 256;

    cudaEventRecord(evFork, 0);
    cudaStreamWaitEvent(side,  evFork, 0);
    cudaStreamWaitEvent(side2, evFork, 0);

    // side: W1 conversion split into n-halves (GEMM1 halves start as each lands), then W2
    convert_cols_kernel<<<colsGrid, 256, 0, side>>>(W1, (__half*)pW1f, 0);
    cudaEventRecord(evW1a, side);
    convert_cols_kernel<<<colsGrid, 256, 0, side>>>(W1, (__half*)pW1f, HID / 2);
    cudaEventRecord(evW1b, side);
    convert_f16_kernel<<<4096, 256, 0, side>>>(W2, (__half*)pW2f, wn4);
    cudaEventRecord(evW2, side);

    // side2: X conversion (overlaps routing chain)
    convertX_kernel<<<(T_TOK * DIM / 4 + 255) / 256, 256, 0, side2>>>(x);
    cudaEventRecord(evX, side2);

    // main (capturing) stream: routing chain
    route_kernel<<<T_TOK / 8, 256>>>(x, Wr, br);
    offsets_kernel<<<1, 1024>>>();
    scatter_kernel<<<T_TOK / 256, 256>>>();

    cudaStreamWaitEvent(0, evX, 0);
    cudaStreamWaitEvent(0, evW1a, 0);
    dim3 g1h(MTILES, HID / BN / 2);   // 72 x 16
    gemm_mma_kernel<DIM, HID, 0><<<g1h, 256, GEMM_SMEM>>>((const __half*)pXf, (const __half*)pW1f, b1, 0);
    cudaStreamWaitEvent(0, evW1b, 0);
    gemm_mma_kernel<DIM, HID, 0><<<g1h, 256, GEMM_SMEM>>>((const __half*)pXf, (const __half*)pW1f, b1, HID / BN / 2);

    cudaStreamWaitEvent(0, evW2, 0);
    dim3 g2(MTILES, DIM / BN);   // 72 x 8
    gemm_mma_kernel<HID, DIM, 1><<<g2, 256, GEMM_SMEM>>>((const __half*)pHf, (const __half*)pW2f, b2, 0);

    combine_kernel<<<(T_TOK * DIM / 4 + 255) / 256, 256>>>(out);

    cudaEventDestroy(evFork);
    cudaEventDestroy(evW1a);
    cudaEventDestroy(evW1b);
    cudaEventDestroy(evW2);
    cudaEventDestroy(evX);
    cudaStreamDestroy(side);
    cudaStreamDestroy(side2);
}

// round 12
// speedup vs baseline: 1.0575x; 1.0575x over previous
#include <cuda_runtime.h>
#include <cuda_fp16.h>
#include <math.h>
#include <stdint.h>

#define T_TOK 4096
#define DIM   1024
#define HID   4096
#define NE    8

#define BM 128
#define BN 128
#define MAX_SLOTS 9216        // 8192 pairs + worst-case per-expert padding, 72 tiles
#define MTILES (MAX_SLOTS/BM)

#define ASTG 10240            // 128 rows * 80 B
#define BSTG 8704             // 32 rows * 272 B
#define NST  3
#define GEMM_SMEM (NST*(ASTG+BSTG))   // 56832 -> 2 CTAs/SM

// ---------------- device scratch (static) ----------------
__device__ int   g_off[NE];
__device__ int   g_cursor[NE];
__device__ int   g_padded_total;
__device__ int   g_sel[T_TOK][2];
__device__ float g_wts[T_TOK][2];
__device__ int   g_slot_tok[MAX_SLOTS];
__device__ int   g_slot_e[MAX_SLOTS];
__device__ float g_slot_w[MAX_SLOTS];
__device__ int   g_tok_slot[T_TOK][2];

__device__ __align__(256) __half g_Xf[T_TOK * DIM];                 // token-major fp16
__device__ __align__(256) __half g_W1f[(size_t)NE * DIM * HID];
__device__ __align__(256) __half g_W2f[(size_t)NE * HID * DIM];
__device__ __align__(256) __half g_Hf[(size_t)MAX_SLOTS * HID];     // slot-major fp16
__device__ __align__(256) __half g_Y[(size_t)MAX_SLOTS * DIM];      // fp16 expert outputs

// ---------------- helpers ----------------
__device__ __forceinline__ uint32_t smem_u32(const void* p) {
    uint32_t a;
    asm("{ .reg .u64 t; cvta.to.shared.u64 t, %1; cvt.u32.u64 %0, t; }" : "=r"(a) : "l"(p));
    return a;
}
__device__ __forceinline__ void cp16(uint32_t dst, const void* src) {
    asm volatile("cp.async.cg.shared.global [%0], [%1], 16;" :: "r"(dst), "l"(src) : "memory");
}
__device__ __forceinline__ void ldm_x4(uint32_t* r, uint32_t addr) {
    asm volatile("ldmatrix.sync.aligned.m8n8.x4.shared.b16 {%0,%1,%2,%3}, [%4];"
                 : "=r"(r[0]), "=r"(r[1]), "=r"(r[2]), "=r"(r[3]) : "r"(addr));
}
__device__ __forceinline__ void ldm_x4_t(uint32_t* r, uint32_t addr) {
    asm volatile("ldmatrix.sync.aligned.m8n8.x4.trans.shared.b16 {%0,%1,%2,%3}, [%4];"
                 : "=r"(r[0]), "=r"(r[1]), "=r"(r[2]), "=r"(r[3]) : "r"(addr));
}
__device__ __forceinline__ void mma16816(float* d, const uint32_t* a, uint32_t b0, uint32_t b1) {
    asm volatile("mma.sync.aligned.m16n8k16.row.col.f32.f16.f16.f32 "
                 "{%0,%1,%2,%3}, {%4,%5,%6,%7}, {%8,%9}, {%0,%1,%2,%3};"
                 : "+f"(d[0]), "+f"(d[1]), "+f"(d[2]), "+f"(d[3])
                 : "r"(a[0]), "r"(a[1]), "r"(a[2]), "r"(a[3]), "r"(b0), "r"(b1));
}
// pack two half2 into one 8-byte store
__device__ __forceinline__ void st_h4(__half* dst, float a, float b, float c, float d) {
    __half2 lo = __floats2half2_rn(a, b);
    __half2 hi = __floats2half2_rn(c, d);
    uint2 pk;
    pk.x = *(uint32_t*)&lo;
    pk.y = *(uint32_t*)&hi;
    *(uint2*)dst = pk;
}

// ---------------- prep kernels ----------------
// 256 threads = 8 tokens/block; Wr staged transposed in smem, x read as coalesced float4
__global__ __launch_bounds__(256) void route_kernel(const float* __restrict__ x,
                                                    const float* __restrict__ Wr,
                                                    const float* __restrict__ br) {
    __shared__ float sW[NE][DIM];       // 32 KB
    __shared__ float sb[NE];
    const int tid = threadIdx.x;

    const float4* Wr4 = (const float4*)Wr;
#pragma unroll
    for (int c = 0; c < 8; c++) {
        int idx = tid + 256 * c;        // 0..2047 float4s = [k][e] pairs
        float4 f = Wr4[idx];
        int k = idx >> 1, e0 = (idx & 1) * 4;
        sW[e0][k] = f.x; sW[e0 + 1][k] = f.y; sW[e0 + 2][k] = f.z; sW[e0 + 3][k] = f.w;
    }
    if (tid < NE) sb[tid] = br[tid];
    __syncthreads();

    const int warp = tid >> 5, lane = tid & 31;
    const int token = blockIdx.x * 8 + warp;
    const float* xr = x + (size_t)token * DIM;

    float acc[NE];
#pragma unroll
    for (int e = 0; e < NE; e++) acc[e] = 0.0f;
#pragma unroll
    for (int i = 0; i < 8; i++) {
        int k = 4 * lane + 128 * i;
        float4 xv = *(const float4*)(xr + k);
#pragma unroll
        for (int e = 0; e < NE; e++) {
            float4 w = *(const float4*)(&sW[e][k]);
            acc[e] += xv.x * w.x + xv.y * w.y + xv.z * w.z + xv.w * w.w;
        }
    }
#pragma unroll
    for (int e = 0; e < NE; e++)
#pragma unroll
        for (int o = 16; o > 0; o >>= 1)
            acc[e] += __shfl_down_sync(0xFFFFFFFFu, acc[e], o);

    if (lane == 0) {
        float l[NE];
#pragma unroll
        for (int e = 0; e < NE; e++) l[e] = acc[e] + sb[e];
        int i0 = 0;
#pragma unroll
        for (int e = 1; e < NE; e++) if (l[e] > l[i0]) i0 = e;
        int i1 = (i0 == 0) ? 1 : 0;
#pragma unroll
        for (int e = 0; e < NE; e++) if (e != i0 && l[e] > l[i1]) i1 = e;
        float w0 = 1.0f / (1.0f + expf(l[i1] - l[i0]));
        g_sel[token][0] = i0; g_sel[token][1] = i1;
        g_wts[token][0] = w0; g_wts[token][1] = 1.0f - w0;
    }
}

// single block: count experts from g_sel, compute padded offsets, init slots & cursors
__global__ __launch_bounds__(1024) void offsets_kernel() {
    __shared__ int wcnt[32][NE];
    __shared__ int soff[NE + 1];
    const int tid = threadIdx.x, wp = tid >> 5, ln = tid & 31;
    if (ln < NE) wcnt[wp][ln] = 0;
    __syncthreads();
    for (int t = tid; t < T_TOK; t += 1024) {
        atomicAdd(&wcnt[wp][g_sel[t][0]], 1);
        atomicAdd(&wcnt[wp][g_sel[t][1]], 1);
    }
    __syncthreads();
    if (tid == 0) {
        int tot = 0;
        for (int e = 0; e < NE; e++) {
            int c = 0;
            for (int w = 0; w < 32; w++) c += wcnt[w][e];
            g_off[e] = tot; soff[e] = tot;
            g_cursor[e] = 0;
            tot += ((c + BM - 1) / BM) * BM;
        }
        soff[NE] = tot;
        g_padded_total = tot;
    }
    __syncthreads();
    int tot = soff[NE];
    for (int s = tid; s < tot; s += 1024) {
        int e = 0;
        while (s >= soff[e + 1]) e++;
        g_slot_e[s] = e;
        g_slot_tok[s] = -1;
    }
}

__global__ void scatter_kernel() {
    int t = blockIdx.x * blockDim.x + threadIdx.x;
    if (t >= T_TOK) return;
#pragma unroll
    for (int j = 0; j < 2; j++) {
        int e = g_sel[t][j];
        int pos = atomicAdd(&g_cursor[e], 1);
        int s = g_off[e] + pos;
        g_slot_tok[s] = t;
        g_slot_w[s] = g_wts[t][j];
        g_tok_slot[t][j] = s;
    }
}

// X fp32 token-major -> fp16 token-major (GEMM1 gathers rows directly)
__global__ void convertX_kernel(const float* __restrict__ x) {
    int idx = blockIdx.x * blockDim.x + threadIdx.x;
    if (idx >= T_TOK * DIM / 4) return;
    float4 v = *(const float4*)(x + (size_t)idx * 4);
    st_h4(g_Xf + (size_t)idx * 4, v.x, v.y, v.z, v.w);
}

__global__ void convert_f16_kernel(const float* __restrict__ src,
                                   __half* __restrict__ dst, size_t n4) {
    size_t idx = blockIdx.x * (size_t)blockDim.x + threadIdx.x;
    size_t stride = (size_t)gridDim.x * blockDim.x;
    for (size_t i = idx; i < n4; i += stride) {
        float4 v = *(const float4*)(src + i * 4);
        st_h4(dst + i * 4, v.x, v.y, v.z, v.w);
    }
}

// ---------------- HMMA GEMM: C[128x128] = A[m,k] * B[k,n], fp16 in / fp32 acc ----------------
// 8 warps, warp grid 4m x 2n, warp tile 32x64. 3-stage cp.async, BK=32, one sync/iter.
// MODE 0: A gathered from token-major g_Xf via slot_tok; +b1, exact GELU -> g_Hf.
// MODE 1: A = g_Hf slot-major; +b2 -> g_Y (fp16).
template<int KD, int NSZ, int MODE>
__global__ __launch_bounds__(256, 2) void gemm_mma_kernel(const __half* __restrict__ A,
                                                          const __half* __restrict__ Bw,
                                                          const float* __restrict__ bias) {
    extern __shared__ char smem[];
    const int m0 = blockIdx.x * BM;
    if (m0 >= g_padded_total) return;
    const int n0 = blockIdx.y * BN;
    const int e  = g_slot_e[m0];
    const __half* B = Bw + (size_t)e * KD * NSZ;

    const int tid = threadIdx.x, wid = tid >> 5, lane = tid & 31;
    const int wm = wid >> 1, wn = wid & 1;
    const uint32_t asb = smem_u32(smem);
    const uint32_t bsb = asb + NST * ASTG;
    constexpr int NT = KD / 32;

    // per-thread load coords (A: 2 x 16B, B: 2 x 16B per thread per stage)
    const int ar  = tid >> 2,         akc  = tid & 3;
    const int ar2 = (tid + 256) >> 2, akc2 = (tid + 256) & 3;
    const int br_ = tid >> 4,         bnc  = tid & 15;
    const int br2 = (tid + 256) >> 4, bnc2 = (tid + 256) & 15;

    // A source row pointers, computed once (MODE 0 gathers via slot_tok)
    const __half *ap0, *ap1;
    if (MODE == 0) {
        int t0 = g_slot_tok[m0 + ar];  if (t0 < 0) t0 = 0;
        int t1 = g_slot_tok[m0 + ar2]; if (t1 < 0) t1 = 0;
        ap0 = A + (size_t)t0 * KD + akc  * 8;
        ap1 = A + (size_t)t1 * KD + akc2 * 8;
    } else {
        ap0 = A + (size_t)(m0 + ar ) * KD + akc  * 8;
        ap1 = A + (size_t)(m0 + ar2) * KD + akc2 * 8;
    }

    float acc[2][8][4];
#pragma unroll
    for (int i = 0; i < 2; i++)
#pragma unroll
        for (int j = 0; j < 8; j++)
#pragma unroll
            for (int q = 0; q < 4; q++) acc[i][j][q] = 0.0f;

#define LOAD_STAGE(KT, BUF) do {                                                           \
    uint32_t ab = asb + (BUF) * ASTG;                                                      \
    uint32_t bb = bsb + (BUF) * BSTG;                                                      \
    cp16(ab + ar  * 80 + akc  * 16, ap0 + (KT) * 32);                                      \
    cp16(ab + ar2 * 80 + akc2 * 16, ap1 + (KT) * 32);                                      \
    cp16(bb + br_ * 272 + bnc  * 16, B + (size_t)((KT) * 32 + br_) * NSZ + n0 + bnc  * 8); \
    cp16(bb + br2 * 272 + bnc2 * 16, B + (size_t)((KT) * 32 + br2) * NSZ + n0 + bnc2 * 8); \
} while (0)

    // prologue: prefetch 2 stages
    LOAD_STAGE(0, 0);
    asm volatile("cp.async.commit_group;" ::: "memory");
    LOAD_STAGE(1, 1);
    asm volatile("cp.async.commit_group;" ::: "memory");

    // ldmatrix base offsets (constant per thread; mapping verified round-3/5)
    const uint32_t a_row_off = (uint32_t)((wm * 32 + (lane & 15)) * 80 + (lane >> 4) * 16);
    const uint32_t b_off = (uint32_t)(((lane & 7) + ((lane >> 3) & 1) * 8) * 272
                                      + (wn * 64 + (lane >> 4) * 8) * 2);

    int cbuf = 0, lbuf = 2;     // compute buffer, load buffer
#pragma unroll 1
    for (int kt = 0; kt < NT; kt++) {
        asm volatile("cp.async.wait_group 1;" ::: "memory");
        __syncthreads();

        if (kt + 2 < NT) LOAD_STAGE(kt + 2, lbuf);
        asm volatile("cp.async.commit_group;" ::: "memory");
        if (++lbuf == NST) lbuf = 0;

        uint32_t ab = asb + cbuf * ASTG;
        uint32_t bb = bsb + cbuf * BSTG;
        if (++cbuf == NST) cbuf = 0;
#pragma unroll
        for (int k16 = 0; k16 < 2; k16++) {
            uint32_t a[2][4];
            ldm_x4(a[0], ab + a_row_off + k16 * 32);
            ldm_x4(a[1], ab + a_row_off + 16 * 80 + k16 * 32);
            uint32_t b[4][4];
#pragma unroll
            for (int p = 0; p < 4; p++)
                ldm_x4_t(b[p], bb + b_off + k16 * 16 * 272 + p * 32);
#pragma unroll
            for (int mt = 0; mt < 2; mt++)
#pragma unroll
                for (int p = 0; p < 4; p++) {
                    mma16816(acc[mt][2 * p],     a[mt], b[p][0], b[p][1]);
                    mma16816(acc[mt][2 * p + 1], a[mt], b[p][2], b[p][3]);
                }
        }
    }
#undef LOAD_STAGE

    // epilogue
    const int group = lane >> 2, tig = lane & 3;
#pragma unroll
    for (int mt = 0; mt < 2; mt++) {
        int r = m0 + wm * 32 + mt * 16 + group;
#pragma unroll
        for (int nt = 0; nt < 8; nt++) {
            int c = n0 + wn * 64 + nt * 8 + tig * 2;
            float b0 = __ldg(bias + (size_t)e * NSZ + c);
            float b1v = __ldg(bias + (size_t)e * NSZ + c + 1);
            float v0 = acc[mt][nt][0] + b0;
            float v1 = acc[mt][nt][1] + b1v;
            float v2 = acc[mt][nt][2] + b0;
            float v3 = acc[mt][nt][3] + b1v;
            if (MODE == 0) {
                v0 = 0.5f * v0 * (1.0f + erff(v0 * 0.70710678118654752f));
                v1 = 0.5f * v1 * (1.0f + erff(v1 * 0.70710678118654752f));
                v2 = 0.5f * v2 * (1.0f + erff(v2 * 0.70710678118654752f));
                v3 = 0.5f * v3 * (1.0f + erff(v3 * 0.70710678118654752f));
                *(__half2*)(g_Hf + (size_t)r * NSZ + c)       = __floats2half2_rn(v0, v1);
                *(__half2*)(g_Hf + (size_t)(r + 8) * NSZ + c) = __floats2half2_rn(v2, v3);
            } else {
                *(__half2*)(g_Y + (size_t)r * NSZ + c)       = __floats2half2_rn(v0, v1);
                *(__half2*)(g_Y + (size_t)(r + 8) * NSZ + c) = __floats2half2_rn(v2, v3);
            }
        }
    }
}

// ---------------- weighted combine (fp16 Y -> fp32 out) ----------------
__global__ void combine_kernel(float* __restrict__ out) {
    int idx = blockIdx.x * blockDim.x + threadIdx.x;
    if (idx >= T_TOK * DIM / 4) return;
    int t = idx >> 8;
    int c = (idx & 255) << 2;
    int s0 = g_tok_slot[t][0], s1 = g_tok_slot[t][1];
    float w0 = g_slot_w[s0], w1 = g_slot_w[s1];
    const __half2* a2 = (const __half2*)(g_Y + (size_t)s0 * DIM + c);
    const __half2* b2 = (const __half2*)(g_Y + (size_t)s1 * DIM + c);
    float2 a01 = __half22float2(a2[0]), a23 = __half22float2(a2[1]);
    float2 b01 = __half22float2(b2[0]), b23 = __half22float2(b2[1]);
    float4 o;
    o.x = w0 * a01.x + w1 * b01.x;
    o.y = w0 * a01.y + w1 * b01.y;
    o.z = w0 * a23.x + w1 * b23.x;
    o.w = w0 * a23.y + w1 * b23.y;
    *(float4*)(out + (size_t)t * DIM + c) = o;
}

// ---------------- host ----------------
extern "C" void kernel_launch(void* const* d_in, const int* in_sizes, int n_in,
                              void* d_out, int out_size) {
    const float* x  = (const float*)d_in[0];
    const float* Wr = (const float*)d_in[1];
    const float* br = (const float*)d_in[2];
    const float* W1 = (const float*)d_in[3];
    const float* b1 = (const float*)d_in[4];
    const float* W2 = (const float*)d_in[5];
    const float* b2 = (const float*)d_in[6];
    float* out = (float*)d_out;

    void* pW1f; cudaGetSymbolAddress(&pW1f, g_W1f);
    void* pW2f; cudaGetSymbolAddress(&pW2f, g_W2f);
    void* pXf;  cudaGetSymbolAddress(&pXf,  g_Xf);
    void* pHf;  cudaGetSymbolAddress(&pHf,  g_Hf);

    cudaFuncSetAttribute(gemm_mma_kernel<DIM, HID, 0>, cudaFuncAttributeMaxDynamicSharedMemorySize, GEMM_SMEM);
    cudaFuncSetAttribute(gemm_mma_kernel<HID, DIM, 1>, cudaFuncAttributeMaxDynamicSharedMemorySize, GEMM_SMEM);

    // side streams forked off the capturing (legacy) stream
    cudaStream_t side, side2;
    cudaStreamCreateWithFlags(&side,  cudaStreamNonBlocking);
    cudaStreamCreateWithFlags(&side2, cudaStreamNonBlocking);
    cudaEvent_t evFork, evW1, evW2, evX;
    cudaEventCreateWithFlags(&evFork, cudaEventDisableTiming);
    cudaEventCreateWithFlags(&evW1,   cudaEventDisableTiming);
    cudaEventCreateWithFlags(&evW2,   cudaEventDisableTiming);
    cudaEventCreateWithFlags(&evX,    cudaEventDisableTiming);

    size_t wn4 = (size_t)NE * DIM * HID / 4;

    cudaEventRecord(evFork, 0);
    cudaStreamWaitEvent(side,  evFork, 0);
    cudaStreamWaitEvent(side2, evFork, 0);

    // side: weight conversions (W1 overlaps prep, W2 overlaps GEMM1)
    convert_f16_kernel<<<4096, 256, 0, side>>>(W1, (__half*)pW1f, wn4);
    cudaEventRecord(evW1, side);
    convert_f16_kernel<<<4096, 256, 0, side>>>(W2, (__half*)pW2f, wn4);
    cudaEventRecord(evW2, side);

    // side2: X conversion (overlaps routing chain)
    convertX_kernel<<<(T_TOK * DIM / 4 + 255) / 256, 256, 0, side2>>>(x);
    cudaEventRecord(evX, side2);

    // main (capturing) stream: routing chain
    route_kernel<<<T_TOK / 8, 256>>>(x, Wr, br);
    offsets_kernel<<<1, 1024>>>();
    scatter_kernel<<<T_TOK / 256, 256>>>();

    cudaStreamWaitEvent(0, evW1, 0);
    cudaStreamWaitEvent(0, evX, 0);
    dim3 g1(MTILES, HID / BN);   // 72 x 32
    gemm_mma_kernel<DIM, HID, 0><<<g1, 256, GEMM_SMEM>>>((const __half*)pXf, (const __half*)pW1f, b1);

    cudaStreamWaitEvent(0, evW2, 0);
    dim3 g2(MTILES, DIM / BN);   // 72 x 8
    gemm_mma_kernel<HID, DIM, 1><<<g2, 256, GEMM_SMEM>>>((const __half*)pHf, (const __half*)pW2f, b2);

    combine_kernel<<<(T_TOK * DIM / 4 + 255) / 256, 256>>>(out);

    cudaEventDestroy(evFork);
    cudaEventDestroy(evW1);
    cudaEventDestroy(evW2);
    cudaEventDestroy(evX);
    cudaStreamDestroy(side);
    cudaStreamDestroy(side2);
}

// round 13
// speedup vs baseline: 1.0752x; 1.0168x over previous
#include <cuda_runtime.h>
#include <cuda_fp16.h>
#include <math.h>
#include <stdint.h>

#define T_TOK 4096
#define DIM   1024
#define HID   4096
#define NE    8

#define BM 128
#define BN 128
#define MAX_SLOTS 9216        // 8192 pairs + worst-case per-expert padding, 72 tiles
#define MTILES (MAX_SLOTS/BM)

#define ASTG 10240            // 128 rows * 80 B
#define BSTG 8704             // 32 rows * 272 B
#define NST  3
#define GEMM_SMEM (NST*(ASTG+BSTG))   // 56832 -> 2 CTAs/SM

// ---------------- device scratch (static) ----------------
__device__ int   g_off[NE];
__device__ int   g_cursor[NE];
__device__ int   g_padded_total;
__device__ int   g_sel[T_TOK][2];
__device__ float g_wts[T_TOK][2];
__device__ int   g_slot_tok[MAX_SLOTS];
__device__ int   g_slot_e[MAX_SLOTS];
__device__ float g_slot_w[MAX_SLOTS];
__device__ int   g_tok_slot[T_TOK][2];

__device__ __align__(256) __half g_Xf[T_TOK * DIM];                 // token-major fp16
__device__ __align__(256) __half g_W1f[(size_t)NE * DIM * HID];
__device__ __align__(256) __half g_W2f[(size_t)NE * HID * DIM];
__device__ __align__(256) __half g_Hf[(size_t)MAX_SLOTS * HID];     // slot-major fp16
__device__ __align__(256) __half g_Y[(size_t)MAX_SLOTS * DIM];      // fp16 expert outputs

// ---------------- helpers ----------------
__device__ __forceinline__ uint32_t smem_u32(const void* p) {
    uint32_t a;
    asm("{ .reg .u64 t; cvta.to.shared.u64 t, %1; cvt.u32.u64 %0, t; }" : "=r"(a) : "l"(p));
    return a;
}
__device__ __forceinline__ void cp16(uint32_t dst, const void* src) {
    asm volatile("cp.async.cg.shared.global [%0], [%1], 16;" :: "r"(dst), "l"(src) : "memory");
}
__device__ __forceinline__ void ldm_x4(uint32_t* r, uint32_t addr) {
    asm volatile("ldmatrix.sync.aligned.m8n8.x4.shared.b16 {%0,%1,%2,%3}, [%4];"
                 : "=r"(r[0]), "=r"(r[1]), "=r"(r[2]), "=r"(r[3]) : "r"(addr));
}
__device__ __forceinline__ void ldm_x4_t(uint32_t* r, uint32_t addr) {
    asm volatile("ldmatrix.sync.aligned.m8n8.x4.trans.shared.b16 {%0,%1,%2,%3}, [%4];"
                 : "=r"(r[0]), "=r"(r[1]), "=r"(r[2]), "=r"(r[3]) : "r"(addr));
}
__device__ __forceinline__ void mma16816(float* d, const uint32_t* a, uint32_t b0, uint32_t b1) {
    asm volatile("mma.sync.aligned.m16n8k16.row.col.f32.f16.f16.f32 "
                 "{%0,%1,%2,%3}, {%4,%5,%6,%7}, {%8,%9}, {%0,%1,%2,%3};"
                 : "+f"(d[0]), "+f"(d[1]), "+f"(d[2]), "+f"(d[3])
                 : "r"(a[0]), "r"(a[1]), "r"(a[2]), "r"(a[3]), "r"(b0), "r"(b1));
}
// pack float4 into one 8-byte fp16x4 value
__device__ __forceinline__ uint2 pack_h4(float4 v) {
    __half2 lo = __floats2half2_rn(v.x, v.y);
    __half2 hi = __floats2half2_rn(v.z, v.w);
    uint2 pk;
    pk.x = *(uint32_t*)&lo;
    pk.y = *(uint32_t*)&hi;
    return pk;
}

// ---------------- prep kernels ----------------
// 256 threads = 8 tokens/block; Wr staged transposed in smem, x read as coalesced float4
__global__ __launch_bounds__(256) void route_kernel(const float* __restrict__ x,
                                                    const float* __restrict__ Wr,
                                                    const float* __restrict__ br) {
    __shared__ float sW[NE][DIM];       // 32 KB
    __shared__ float sb[NE];
    const int tid = threadIdx.x;

    const float4* Wr4 = (const float4*)Wr;
#pragma unroll
    for (int c = 0; c < 8; c++) {
        int idx = tid + 256 * c;        // 0..2047 float4s = [k][e] pairs
        float4 f = Wr4[idx];
        int k = idx >> 1, e0 = (idx & 1) * 4;
        sW[e0][k] = f.x; sW[e0 + 1][k] = f.y; sW[e0 + 2][k] = f.z; sW[e0 + 3][k] = f.w;
    }
    if (tid < NE) sb[tid] = br[tid];
    __syncthreads();

    const int warp = tid >> 5, lane = tid & 31;
    const int token = blockIdx.x * 8 + warp;
    const float* xr = x + (size_t)token * DIM;

    float acc[NE];
#pragma unroll
    for (int e = 0; e < NE; e++) acc[e] = 0.0f;
#pragma unroll
    for (int i = 0; i < 8; i++) {
        int k = 4 * lane + 128 * i;
        float4 xv = *(const float4*)(xr + k);
#pragma unroll
        for (int e = 0; e < NE; e++) {
            float4 w = *(const float4*)(&sW[e][k]);
            acc[e] += xv.x * w.x + xv.y * w.y + xv.z * w.z + xv.w * w.w;
        }
    }
#pragma unroll
    for (int e = 0; e < NE; e++)
#pragma unroll
        for (int o = 16; o > 0; o >>= 1)
            acc[e] += __shfl_down_sync(0xFFFFFFFFu, acc[e], o);

    if (lane == 0) {
        float l[NE];
#pragma unroll
        for (int e = 0; e < NE; e++) l[e] = acc[e] + sb[e];
        int i0 = 0;
#pragma unroll
        for (int e = 1; e < NE; e++) if (l[e] > l[i0]) i0 = e;
        int i1 = (i0 == 0) ? 1 : 0;
#pragma unroll
        for (int e = 0; e < NE; e++) if (e != i0 && l[e] > l[i1]) i1 = e;
        float w0 = 1.0f / (1.0f + expf(l[i1] - l[i0]));
        g_sel[token][0] = i0; g_sel[token][1] = i1;
        g_wts[token][0] = w0; g_wts[token][1] = 1.0f - w0;
    }
}

// single block: count experts from g_sel, compute padded offsets, init slots & cursors
__global__ __launch_bounds__(1024) void offsets_kernel() {
    __shared__ int wcnt[32][NE];
    __shared__ int soff[NE + 1];
    const int tid = threadIdx.x, wp = tid >> 5, ln = tid & 31;
    if (ln < NE) wcnt[wp][ln] = 0;
    __syncthreads();
    for (int t = tid; t < T_TOK; t += 1024) {
        atomicAdd(&wcnt[wp][g_sel[t][0]], 1);
        atomicAdd(&wcnt[wp][g_sel[t][1]], 1);
    }
    __syncthreads();
    if (tid == 0) {
        int tot = 0;
        for (int e = 0; e < NE; e++) {
            int c = 0;
            for (int w = 0; w < 32; w++) c += wcnt[w][e];
            g_off[e] = tot; soff[e] = tot;
            g_cursor[e] = 0;
            tot += ((c + BM - 1) / BM) * BM;
        }
        soff[NE] = tot;
        g_padded_total = tot;
    }
    __syncthreads();
    int tot = soff[NE];
    for (int s = tid; s < tot; s += 1024) {
        int e = 0;
        while (s >= soff[e + 1]) e++;
        g_slot_e[s] = e;
        g_slot_tok[s] = -1;
    }
}

__global__ void scatter_kernel() {
    int t = blockIdx.x * blockDim.x + threadIdx.x;
    if (t >= T_TOK) return;
#pragma unroll
    for (int j = 0; j < 2; j++) {
        int e = g_sel[t][j];
        int pos = atomicAdd(&g_cursor[e], 1);
        int s = g_off[e] + pos;
        g_slot_tok[s] = t;
        g_slot_w[s] = g_wts[t][j];
        g_tok_slot[t][j] = s;
    }
}

// X fp32 -> fp16, 4 independent float4s per thread (MLP=4); grid*block*4 == T_TOK*DIM/4
__global__ void convertX_kernel(const float* __restrict__ x) {
    const size_t stride = (size_t)gridDim.x * blockDim.x;
    size_t i = blockIdx.x * (size_t)blockDim.x + threadIdx.x;
    const float4* src = (const float4*)x;
    uint2* dst = (uint2*)g_Xf;
    float4 v[4];
#pragma unroll
    for (int j = 0; j < 4; j++) v[j] = src[i + j * stride];
#pragma unroll
    for (int j = 0; j < 4; j++) dst[i + j * stride] = pack_h4(v[j]);
}

// W fp32 -> fp16, 8 independent float4s per thread (MLP=8); grid*block*8 == n4
__global__ void convert_f16_kernel(const float* __restrict__ srcf,
                                   __half* __restrict__ dsth) {
    const size_t stride = (size_t)gridDim.x * blockDim.x;
    size_t i = blockIdx.x * (size_t)blockDim.x + threadIdx.x;
    const float4* src = (const float4*)srcf;
    uint2* dst = (uint2*)dsth;
    float4 v[8];
#pragma unroll
    for (int j = 0; j < 8; j++) v[j] = src[i + j * stride];
#pragma unroll
    for (int j = 0; j < 8; j++) dst[i + j * stride] = pack_h4(v[j]);
}

// ---------------- HMMA GEMM: C[128x128] = A[m,k] * B[k,n], fp16 in / fp32 acc ----------------
// 8 warps, warp grid 4m x 2n, warp tile 32x64. 3-stage cp.async, BK=32, one sync/iter.
// MODE 0: A gathered from token-major g_Xf via slot_tok; +b1, exact GELU -> g_Hf.
// MODE 1: A = g_Hf slot-major; +b2 -> g_Y (fp16).
template<int KD, int NSZ, int MODE>
__global__ __launch_bounds__(256, 2) void gemm_mma_kernel(const __half* __restrict__ A,
                                                          const __half* __restrict__ Bw,
                                                          const float* __restrict__ bias) {
    extern __shared__ char smem[];
    const int m0 = blockIdx.x * BM;
    if (m0 >= g_padded_total) return;
    const int n0 = blockIdx.y * BN;
    const int e  = g_slot_e[m0];
    const __half* B = Bw + (size_t)e * KD * NSZ;

    const int tid = threadIdx.x, wid = tid >> 5, lane = tid & 31;
    const int wm = wid >> 1, wn = wid & 1;
    const uint32_t asb = smem_u32(smem);
    const uint32_t bsb = asb + NST * ASTG;
    constexpr int NT = KD / 32;

    // per-thread load coords (A: 2 x 16B, B: 2 x 16B per thread per stage)
    const int ar  = tid >> 2,         akc  = tid & 3;
    const int ar2 = (tid + 256) >> 2, akc2 = (tid + 256) & 3;
    const int br_ = tid >> 4,         bnc  = tid & 15;
    const int br2 = (tid + 256) >> 4, bnc2 = (tid + 256) & 15;

    // A source row pointers, computed once (MODE 0 gathers via slot_tok)
    const __half *ap0, *ap1;
    if (MODE == 0) {
        int t0 = g_slot_tok[m0 + ar];  if (t0 < 0) t0 = 0;
        int t1 = g_slot_tok[m0 + ar2]; if (t1 < 0) t1 = 0;
        ap0 = A + (size_t)t0 * KD + akc  * 8;
        ap1 = A + (size_t)t1 * KD + akc2 * 8;
    } else {
        ap0 = A + (size_t)(m0 + ar ) * KD + akc  * 8;
        ap1 = A + (size_t)(m0 + ar2) * KD + akc2 * 8;
    }

    float acc[2][8][4];
#pragma unroll
    for (int i = 0; i < 2; i++)
#pragma unroll
        for (int j = 0; j < 8; j++)
#pragma unroll
            for (int q = 0; q < 4; q++) acc[i][j][q] = 0.0f;

#define LOAD_STAGE(KT, BUF) do {                                                           \
    uint32_t ab = asb + (BUF) * ASTG;                                                      \
    uint32_t bb = bsb + (BUF) * BSTG;                                                      \
    cp16(ab + ar  * 80 + akc  * 16, ap0 + (KT) * 32);                                      \
    cp16(ab + ar2 * 80 + akc2 * 16, ap1 + (KT) * 32);                                      \
    cp16(bb + br_ * 272 + bnc  * 16, B + (size_t)((KT) * 32 + br_) * NSZ + n0 + bnc  * 8); \
    cp16(bb + br2 * 272 + bnc2 * 16, B + (size_t)((KT) * 32 + br2) * NSZ + n0 + bnc2 * 8); \
} while (0)

    // prologue: prefetch 2 stages
    LOAD_STAGE(0, 0);
    asm volatile("cp.async.commit_group;" ::: "memory");
    LOAD_STAGE(1, 1);
    asm volatile("cp.async.commit_group;" ::: "memory");

    // ldmatrix base offsets (constant per thread; mapping verified round-3/5)
    const uint32_t a_row_off = (uint32_t)((wm * 32 + (lane & 15)) * 80 + (lane >> 4) * 16);
    const uint32_t b_off = (uint32_t)(((lane & 7) + ((lane >> 3) & 1) * 8) * 272
                                      + (wn * 64 + (lane >> 4) * 8) * 2);

    int cbuf = 0, lbuf = 2;     // compute buffer, load buffer
#pragma unroll 1
    for (int kt = 0; kt < NT; kt++) {
        asm volatile("cp.async.wait_group 1;" ::: "memory");
        __syncthreads();

        if (kt + 2 < NT) LOAD_STAGE(kt + 2, lbuf);
        asm volatile("cp.async.commit_group;" ::: "memory");
        if (++lbuf == NST) lbuf = 0;

        uint32_t ab = asb + cbuf * ASTG;
        uint32_t bb = bsb + cbuf * BSTG;
        if (++cbuf == NST) cbuf = 0;
#pragma unroll
        for (int k16 = 0; k16 < 2; k16++) {
            uint32_t a[2][4];
            ldm_x4(a[0], ab + a_row_off + k16 * 32);
            ldm_x4(a[1], ab + a_row_off + 16 * 80 + k16 * 32);
            uint32_t b[4][4];
#pragma unroll
            for (int p = 0; p < 4; p++)
                ldm_x4_t(b[p], bb + b_off + k16 * 16 * 272 + p * 32);
#pragma unroll
            for (int mt = 0; mt < 2; mt++)
#pragma unroll
                for (int p = 0; p < 4; p++) {
                    mma16816(acc[mt][2 * p],     a[mt], b[p][0], b[p][1]);
                    mma16816(acc[mt][2 * p + 1], a[mt], b[p][2], b[p][3]);
                }
        }
    }
#undef LOAD_STAGE

    // epilogue
    const int group = lane >> 2, tig = lane & 3;
#pragma unroll
    for (int mt = 0; mt < 2; mt++) {
        int r = m0 + wm * 32 + mt * 16 + group;
#pragma unroll
        for (int nt = 0; nt < 8; nt++) {
            int c = n0 + wn * 64 + nt * 8 + tig * 2;
            float b0 = __ldg(bias + (size_t)e * NSZ + c);
            float b1v = __ldg(bias + (size_t)e * NSZ + c + 1);
            float v0 = acc[mt][nt][0] + b0;
            float v1 = acc[mt][nt][1] + b1v;
            float v2 = acc[mt][nt][2] + b0;
            float v3 = acc[mt][nt][3] + b1v;
            if (MODE == 0) {
                v0 = 0.5f * v0 * (1.0f + erff(v0 * 0.70710678118654752f));
                v1 = 0.5f * v1 * (1.0f + erff(v1 * 0.70710678118654752f));
                v2 = 0.5f * v2 * (1.0f + erff(v2 * 0.70710678118654752f));
                v3 = 0.5f * v3 * (1.0f + erff(v3 * 0.70710678118654752f));
                *(__half2*)(g_Hf + (size_t)r * NSZ + c)       = __floats2half2_rn(v0, v1);
                *(__half2*)(g_Hf + (size_t)(r + 8) * NSZ + c) = __floats2half2_rn(v2, v3);
            } else {
                *(__half2*)(g_Y + (size_t)r * NSZ + c)       = __floats2half2_rn(v0, v1);
                *(__half2*)(g_Y + (size_t)(r + 8) * NSZ + c) = __floats2half2_rn(v2, v3);
            }
        }
    }
}

// ---------------- weighted combine (fp16 Y -> fp32 out), 4 chunks/thread ----------------
__global__ void combine_kernel(float* __restrict__ out) {
    const int stride = gridDim.x * blockDim.x;
    int idx = blockIdx.x * blockDim.x + threadIdx.x;
#pragma unroll
    for (int j = 0; j < 4; j++, idx += stride) {
        int t = idx >> 8;
        int c = (idx & 255) << 2;
        int s0 = g_tok_slot[t][0], s1 = g_tok_slot[t][1];
        float w0 = g_slot_w[s0], w1 = g_slot_w[s1];
        const __half2* a2 = (const __half2*)(g_Y + (size_t)s0 * DIM + c);
        const __half2* b2 = (const __half2*)(g_Y + (size_t)s1 * DIM + c);
        float2 a01 = __half22float2(a2[0]), a23 = __half22float2(a2[1]);
        float2 b01 = __half22float2(b2[0]), b23 = __half22float2(b2[1]);
        float4 o;
        o.x = w0 * a01.x + w1 * b01.x;
        o.y = w0 * a01.y + w1 * b01.y;
        o.z = w0 * a23.x + w1 * b23.x;
        o.w = w0 * a23.y + w1 * b23.y;
        *(float4*)(out + (size_t)t * DIM + c) = o;
    }
}

// ---------------- host ----------------
extern "C" void kernel_launch(void* const* d_in, const int* in_sizes, int n_in,
                              void* d_out, int out_size) {
    const float* x  = (const float*)d_in[0];
    const float* Wr = (const float*)d_in[1];
    const float* br = (const float*)d_in[2];
    const float* W1 = (const float*)d_in[3];
    const float* b1 = (const float*)d_in[4];
    const float* W2 = (const float*)d_in[5];
    const float* b2 = (const float*)d_in[6];
    float* out = (float*)d_out;

    void* pW1f; cudaGetSymbolAddress(&pW1f, g_W1f);
    void* pW2f; cudaGetSymbolAddress(&pW2f, g_W2f);
    void* pXf;  cudaGetSymbolAddress(&pXf,  g_Xf);
    void* pHf;  cudaGetSymbolAddress(&pHf,  g_Hf);

    cudaFuncSetAttribute(gemm_mma_kernel<DIM, HID, 0>, cudaFuncAttributeMaxDynamicSharedMemorySize, GEMM_SMEM);
    cudaFuncSetAttribute(gemm_mma_kernel<HID, DIM, 1>, cudaFuncAttributeMaxDynamicSharedMemorySize, GEMM_SMEM);

    // side streams forked off the capturing (legacy) stream
    cudaStream_t side, side2;
    cudaStreamCreateWithFlags(&side,  cudaStreamNonBlocking);
    cudaStreamCreateWithFlags(&side2, cudaStreamNonBlocking);
    cudaEvent_t evFork, evW1, evW2, evX;
    cudaEventCreateWithFlags(&evFork, cudaEventDisableTiming);
    cudaEventCreateWithFlags(&evW1,   cudaEventDisableTiming);
    cudaEventCreateWithFlags(&evW2,   cudaEventDisableTiming);
    cudaEventCreateWithFlags(&evX,    cudaEventDisableTiming);

    // n4(W) = 8,388,608 float4s; 8/thread -> 4096 CTAs x 256 exactly
    const int wGrid = (int)((size_t)NE * DIM * HID / 4 / (8 * 256));
    // n4(X) = 1,048,576 float4s; 4/thread -> 1024 CTAs x 256 exactly
    const int xGrid = T_TOK * DIM / 4 / (4 * 256);

    cudaEventRecord(evFork, 0);
    cudaStreamWaitEvent(side,  evFork, 0);
    cudaStreamWaitEvent(side2, evFork, 0);

    // side: weight conversions (W1 overlaps prep, W2 overlaps GEMM1)
    convert_f16_kernel<<<wGrid, 256, 0, side>>>(W1, (__half*)pW1f);
    cudaEventRecord(evW1, side);
    convert_f16_kernel<<<wGrid, 256, 0, side>>>(W2, (__half*)pW2f);
    cudaEventRecord(evW2, side);

    // side2: X conversion (overlaps routing chain)
    convertX_kernel<<<xGrid, 256, 0, side2>>>(x);
    cudaEventRecord(evX, side2);

    // main (capturing) stream: routing chain
    route_kernel<<<T_TOK / 8, 256>>>(x, Wr, br);
    offsets_kernel<<<1, 1024>>>();
    scatter_kernel<<<T_TOK / 256, 256>>>();

    cudaStreamWaitEvent(0, evW1, 0);
    cudaStreamWaitEvent(0, evX, 0);
    dim3 g1(MTILES, HID / BN);   // 72 x 32
    gemm_mma_kernel<DIM, HID, 0><<<g1, 256, GEMM_SMEM>>>((const __half*)pXf, (const __half*)pW1f, b1);

    cudaStreamWaitEvent(0, evW2, 0);
    dim3 g2(MTILES, DIM / BN);   // 72 x 8
    gemm_mma_kernel<HID, DIM, 1><<<g2, 256, GEMM_SMEM>>>((const __half*)pHf, (const __half*)pW2f, b2);

    combine_kernel<<<T_TOK * DIM / 4 / (4 * 256), 256>>>(out);

    cudaEventDestroy(evFork);
    cudaEventDestroy(evW1);
    cudaEventDestroy(evW2);
    cudaEventDestroy(evX);
    cudaStreamDestroy(side);
    cudaStreamDestroy(side2);
}

// round 14
// speedup vs baseline: 1.0754x; 1.0001x over previous
#include <cuda_runtime.h>
#include <cuda_fp16.h>
#include <math.h>
#include <stdint.h>

#define T_TOK 4096
#define DIM   1024
#define HID   4096
#define NE    8

#define BM 128
#define BN 128
#define MAX_SLOTS 9216        // 8192 pairs + worst-case per-expert padding, 72 tiles
#define MTILES (MAX_SLOTS/BM)

#define ASTG 10240            // 128 rows * 80 B
#define BSTG 8704             // 32 rows * 272 B
#define NST  3
#define GEMM_SMEM (NST*(ASTG+BSTG))   // 56832 -> 2 CTAs/SM

// ---------------- device scratch (static) ----------------
__device__ int   g_off[NE];
__device__ int   g_cursor[NE];
__device__ int   g_padded_total;
__device__ int   g_sel[T_TOK][2];
__device__ float g_wts[T_TOK][2];
__device__ int   g_slot_tok[MAX_SLOTS];
__device__ int   g_slot_e[MAX_SLOTS];
__device__ float g_slot_w[MAX_SLOTS];
__device__ int   g_tok_slot[T_TOK][2];

__device__ __align__(256) __half g_Xf[T_TOK * DIM];                 // token-major fp16
__device__ __align__(256) __half g_W1f[(size_t)NE * DIM * HID];
__device__ __align__(256) __half g_W2f[(size_t)NE * HID * DIM];
__device__ __align__(256) __half g_Hf[(size_t)MAX_SLOTS * HID];     // slot-major fp16
__device__ __align__(256) __half g_Y[(size_t)MAX_SLOTS * DIM];      // fp16 expert outputs

// ---------------- helpers ----------------
__device__ __forceinline__ uint32_t smem_u32(const void* p) {
    uint32_t a;
    asm("{ .reg .u64 t; cvta.to.shared.u64 t, %1; cvt.u32.u64 %0, t; }" : "=r"(a) : "l"(p));
    return a;
}
__device__ __forceinline__ void cp16(uint32_t dst, const void* src) {
    asm volatile("cp.async.cg.shared.global [%0], [%1], 16;" :: "r"(dst), "l"(src) : "memory");
}
__device__ __forceinline__ void ldm_x4(uint32_t* r, uint32_t addr) {
    asm volatile("ldmatrix.sync.aligned.m8n8.x4.shared.b16 {%0,%1,%2,%3}, [%4];"
                 : "=r"(r[0]), "=r"(r[1]), "=r"(r[2]), "=r"(r[3]) : "r"(addr));
}
__device__ __forceinline__ void ldm_x4_t(uint32_t* r, uint32_t addr) {
    asm volatile("ldmatrix.sync.aligned.m8n8.x4.trans.shared.b16 {%0,%1,%2,%3}, [%4];"
                 : "=r"(r[0]), "=r"(r[1]), "=r"(r[2]), "=r"(r[3]) : "r"(addr));
}
__device__ __forceinline__ void mma16816(float* d, const uint32_t* a, uint32_t b0, uint32_t b1) {
    asm volatile("mma.sync.aligned.m16n8k16.row.col.f32.f16.f16.f32 "
                 "{%0,%1,%2,%3}, {%4,%5,%6,%7}, {%8,%9}, {%0,%1,%2,%3};"
                 : "+f"(d[0]), "+f"(d[1]), "+f"(d[2]), "+f"(d[3])
                 : "r"(a[0]), "r"(a[1]), "r"(a[2]), "r"(a[3]), "r"(b0), "r"(b1));
}
// pack float4 into one 8-byte fp16x4 value
__device__ __forceinline__ uint2 pack_h4(float4 v) {
    __half2 lo = __floats2half2_rn(v.x, v.y);
    __half2 hi = __floats2half2_rn(v.z, v.w);
    uint2 pk;
    pk.x = *(uint32_t*)&lo;
    pk.y = *(uint32_t*)&hi;
    return pk;
}

// ---------------- prep kernels ----------------
// 256 threads = 8 warps x 4 tokens each; Wr staged transposed in smem (MLP=4 x-streams)
__global__ __launch_bounds__(256) void route_kernel(const float* __restrict__ x,
                                                    const float* __restrict__ Wr,
                                                    const float* __restrict__ br) {
    __shared__ float sW[NE][DIM];       // 32 KB
    __shared__ float sb[NE];
    const int tid = threadIdx.x;

    const float4* Wr4 = (const float4*)Wr;
#pragma unroll
    for (int c = 0; c < 8; c++) {
        int idx = tid + 256 * c;        // 0..2047 float4s = [k][e] pairs
        float4 f = Wr4[idx];
        int k = idx >> 1, e0 = (idx & 1) * 4;
        sW[e0][k] = f.x; sW[e0 + 1][k] = f.y; sW[e0 + 2][k] = f.z; sW[e0 + 3][k] = f.w;
    }
    if (tid < NE) sb[tid] = br[tid];
    __syncthreads();

    const int warp = tid >> 5, lane = tid & 31;
    const int tok0 = blockIdx.x * 32 + warp * 4;     // 4 tokens per warp
    const float* xr0 = x + (size_t)tok0 * DIM;

    float acc[4][NE];
#pragma unroll
    for (int t = 0; t < 4; t++)
#pragma unroll
        for (int e = 0; e < NE; e++) acc[t][e] = 0.0f;

#pragma unroll
    for (int i = 0; i < 8; i++) {
        int k = 4 * lane + 128 * i;
        float4 xv[4];
#pragma unroll
        for (int t = 0; t < 4; t++)
            xv[t] = *(const float4*)(xr0 + (size_t)t * DIM + k);
#pragma unroll
        for (int e = 0; e < NE; e++) {
            float4 w = *(const float4*)(&sW[e][k]);
#pragma unroll
            for (int t = 0; t < 4; t++)
                acc[t][e] += xv[t].x * w.x + xv[t].y * w.y + xv[t].z * w.z + xv[t].w * w.w;
        }
    }
#pragma unroll
    for (int t = 0; t < 4; t++)
#pragma unroll
        for (int e = 0; e < NE; e++)
#pragma unroll
            for (int o = 16; o > 0; o >>= 1)
                acc[t][e] += __shfl_down_sync(0xFFFFFFFFu, acc[t][e], o);

    if (lane == 0) {
#pragma unroll
        for (int t = 0; t < 4; t++) {
            float l[NE];
#pragma unroll
            for (int e = 0; e < NE; e++) l[e] = acc[t][e] + sb[e];
            int i0 = 0;
#pragma unroll
            for (int e = 1; e < NE; e++) if (l[e] > l[i0]) i0 = e;
            int i1 = (i0 == 0) ? 1 : 0;
#pragma unroll
            for (int e = 0; e < NE; e++) if (e != i0 && l[e] > l[i1]) i1 = e;
            float w0 = 1.0f / (1.0f + expf(l[i1] - l[i0]));
            int token = tok0 + t;
            g_sel[token][0] = i0; g_sel[token][1] = i1;
            g_wts[token][0] = w0; g_wts[token][1] = 1.0f - w0;
        }
    }
}

// single block: count experts from g_sel, compute padded offsets, init slots & cursors
__global__ __launch_bounds__(1024) void offsets_kernel() {
    __shared__ int wcnt[32][NE];
    __shared__ int soff[NE + 1];
    const int tid = threadIdx.x, wp = tid >> 5, ln = tid & 31;
    if (ln < NE) wcnt[wp][ln] = 0;
    __syncthreads();
    for (int t = tid; t < T_TOK; t += 1024) {
        atomicAdd(&wcnt[wp][g_sel[t][0]], 1);
        atomicAdd(&wcnt[wp][g_sel[t][1]], 1);
    }
    __syncthreads();
    if (tid == 0) {
        int tot = 0;
        for (int e = 0; e < NE; e++) {
            int c = 0;
            for (int w = 0; w < 32; w++) c += wcnt[w][e];
            g_off[e] = tot; soff[e] = tot;
            g_cursor[e] = 0;
            tot += ((c + BM - 1) / BM) * BM;
        }
        soff[NE] = tot;
        g_padded_total = tot;
    }
    __syncthreads();
    int tot = soff[NE];
    for (int s = tid; s < tot; s += 1024) {
        int e = 0;
        while (s >= soff[e + 1]) e++;
        g_slot_e[s] = e;
        g_slot_tok[s] = -1;
    }
}

__global__ void scatter_kernel() {
    int t = blockIdx.x * blockDim.x + threadIdx.x;
    if (t >= T_TOK) return;
#pragma unroll
    for (int j = 0; j < 2; j++) {
        int e = g_sel[t][j];
        int pos = atomicAdd(&g_cursor[e], 1);
        int s = g_off[e] + pos;
        g_slot_tok[s] = t;
        g_slot_w[s] = g_wts[t][j];
        g_tok_slot[t][j] = s;
    }
}

// X fp32 -> fp16, 4 independent float4s per thread (MLP=4); grid*block*4 == T_TOK*DIM/4
__global__ void convertX_kernel(const float* __restrict__ x) {
    const size_t stride = (size_t)gridDim.x * blockDim.x;
    size_t i = blockIdx.x * (size_t)blockDim.x + threadIdx.x;
    const float4* src = (const float4*)x;
    uint2* dst = (uint2*)g_Xf;
    float4 v[4];
#pragma unroll
    for (int j = 0; j < 4; j++) v[j] = src[i + j * stride];
#pragma unroll
    for (int j = 0; j < 4; j++) dst[i + j * stride] = pack_h4(v[j]);
}

// W fp32 -> fp16, 8 independent float4s per thread (MLP=8); grid*block*8 == n4
__global__ void convert_f16_kernel(const float* __restrict__ srcf,
                                   __half* __restrict__ dsth) {
    const size_t stride = (size_t)gridDim.x * blockDim.x;
    size_t i = blockIdx.x * (size_t)blockDim.x + threadIdx.x;
    const float4* src = (const float4*)srcf;
    uint2* dst = (uint2*)dsth;
    float4 v[8];
#pragma unroll
    for (int j = 0; j < 8; j++) v[j] = src[i + j * stride];
#pragma unroll
    for (int j = 0; j < 8; j++) dst[i + j * stride] = pack_h4(v[j]);
}

// ---------------- HMMA GEMM: C[128x128] = A[m,k] * B[k,n], fp16 in / fp32 acc ----------------
// 8 warps, warp grid 4m x 2n, warp tile 32x64. 3-stage cp.async, BK=32, one sync/iter.
// MODE 0: A gathered from token-major g_Xf via slot_tok; +b1, exact GELU -> g_Hf.
// MODE 1: A = g_Hf slot-major; +b2 -> g_Y (fp16).
template<int KD, int NSZ, int MODE>
__global__ __launch_bounds__(256, 2) void gemm_mma_kernel(const __half* __restrict__ A,
                                                          const __half* __restrict__ Bw,
                                                          const float* __restrict__ bias) {
    extern __shared__ char smem[];
    const int m0 = blockIdx.x * BM;
    if (m0 >= g_padded_total) return;
    const int n0 = blockIdx.y * BN;
    const int e  = g_slot_e[m0];
    const __half* B = Bw + (size_t)e * KD * NSZ;

    const int tid = threadIdx.x, wid = tid >> 5, lane = tid & 31;
    const int wm = wid >> 1, wn = wid & 1;
    const uint32_t asb = smem_u32(smem);
    const uint32_t bsb = asb + NST * ASTG;
    constexpr int NT = KD / 32;

    // per-thread load coords (A: 2 x 16B, B: 2 x 16B per thread per stage)
    const int ar  = tid >> 2,         akc  = tid & 3;
    const int ar2 = (tid + 256) >> 2, akc2 = (tid + 256) & 3;
    const int br_ = tid >> 4,         bnc  = tid & 15;
    const int br2 = (tid + 256) >> 4, bnc2 = (tid + 256) & 15;

    // A source row pointers, computed once (MODE 0 gathers via slot_tok)
    const __half *ap0, *ap1;
    if (MODE == 0) {
        int t0 = g_slot_tok[m0 + ar];  if (t0 < 0) t0 = 0;
        int t1 = g_slot_tok[m0 + ar2]; if (t1 < 0) t1 = 0;
        ap0 = A + (size_t)t0 * KD + akc  * 8;
        ap1 = A + (size_t)t1 * KD + akc2 * 8;
    } else {
        ap0 = A + (size_t)(m0 + ar ) * KD + akc  * 8;
        ap1 = A + (size_t)(m0 + ar2) * KD + akc2 * 8;
    }

    float acc[2][8][4];
#pragma unroll
    for (int i = 0; i < 2; i++)
#pragma unroll
        for (int j = 0; j < 8; j++)
#pragma unroll
            for (int q = 0; q < 4; q++) acc[i][j][q] = 0.0f;

#define LOAD_STAGE(KT, BUF) do {                                                           \
    uint32_t ab = asb + (BUF) * ASTG;                                                      \
    uint32_t bb = bsb + (BUF) * BSTG;                                                      \
    cp16(ab + ar  * 80 + akc  * 16, ap0 + (KT) * 32);                                      \
    cp16(ab + ar2 * 80 + akc2 * 16, ap1 + (KT) * 32);                                      \
    cp16(bb + br_ * 272 + bnc  * 16, B + (size_t)((KT) * 32 + br_) * NSZ + n0 + bnc  * 8); \
    cp16(bb + br2 * 272 + bnc2 * 16, B + (size_t)((KT) * 32 + br2) * NSZ + n0 + bnc2 * 8); \
} while (0)

    // prologue: prefetch 2 stages
    LOAD_STAGE(0, 0);
    asm volatile("cp.async.commit_group;" ::: "memory");
    LOAD_STAGE(1, 1);
    asm volatile("cp.async.commit_group;" ::: "memory");

    // ldmatrix base offsets (constant per thread; mapping verified round-3/5)
    const uint32_t a_row_off = (uint32_t)((wm * 32 + (lane & 15)) * 80 + (lane >> 4) * 16);
    const uint32_t b_off = (uint32_t)(((lane & 7) + ((lane >> 3) & 1) * 8) * 272
                                      + (wn * 64 + (lane >> 4) * 8) * 2);

    int cbuf = 0, lbuf = 2;     // compute buffer, load buffer
#pragma unroll 1
    for (int kt = 0; kt < NT; kt++) {
        asm volatile("cp.async.wait_group 1;" ::: "memory");
        __syncthreads();

        if (kt + 2 < NT) LOAD_STAGE(kt + 2, lbuf);
        asm volatile("cp.async.commit_group;" ::: "memory");
        if (++lbuf == NST) lbuf = 0;

        uint32_t ab = asb + cbuf * ASTG;
        uint32_t bb = bsb + cbuf * BSTG;
        if (++cbuf == NST) cbuf = 0;
#pragma unroll
        for (int k16 = 0; k16 < 2; k16++) {
            uint32_t a[2][4];
            ldm_x4(a[0], ab + a_row_off + k16 * 32);
            ldm_x4(a[1], ab + a_row_off + 16 * 80 + k16 * 32);
            uint32_t b[4][4];
#pragma unroll
            for (int p = 0; p < 4; p++)
                ldm_x4_t(b[p], bb + b_off + k16 * 16 * 272 + p * 32);
#pragma unroll
            for (int mt = 0; mt < 2; mt++)
#pragma unroll
                for (int p = 0; p < 4; p++) {
                    mma16816(acc[mt][2 * p],     a[mt], b[p][0], b[p][1]);
                    mma16816(acc[mt][2 * p + 1], a[mt], b[p][2], b[p][3]);
                }
        }
    }
#undef LOAD_STAGE

    // epilogue
    const int group = lane >> 2, tig = lane & 3;
#pragma unroll
    for (int mt = 0; mt < 2; mt++) {
        int r = m0 + wm * 32 + mt * 16 + group;
#pragma unroll
        for (int nt = 0; nt < 8; nt++) {
            int c = n0 + wn * 64 + nt * 8 + tig * 2;
            float b0 = __ldg(bias + (size_t)e * NSZ + c);
            float b1v = __ldg(bias + (size_t)e * NSZ + c + 1);
            float v0 = acc[mt][nt][0] + b0;
            float v1 = acc[mt][nt][1] + b1v;
            float v2 = acc[mt][nt][2] + b0;
            float v3 = acc[mt][nt][3] + b1v;
            if (MODE == 0) {
                v0 = 0.5f * v0 * (1.0f + erff(v0 * 0.70710678118654752f));
                v1 = 0.5f * v1 * (1.0f + erff(v1 * 0.70710678118654752f));
                v2 = 0.5f * v2 * (1.0f + erff(v2 * 0.70710678118654752f));
                v3 = 0.5f * v3 * (1.0f + erff(v3 * 0.70710678118654752f));
                *(__half2*)(g_Hf + (size_t)r * NSZ + c)       = __floats2half2_rn(v0, v1);
                *(__half2*)(g_Hf + (size_t)(r + 8) * NSZ + c) = __floats2half2_rn(v2, v3);
            } else {
                *(__half2*)(g_Y + (size_t)r * NSZ + c)       = __floats2half2_rn(v0, v1);
                *(__half2*)(g_Y + (size_t)(r + 8) * NSZ + c) = __floats2half2_rn(v2, v3);
            }
        }
    }
}

// ---------------- weighted combine (fp16 Y -> fp32 out), 4 chunks/thread ----------------
__global__ void combine_kernel(float* __restrict__ out) {
    const int stride = gridDim.x * blockDim.x;
    int idx = blockIdx.x * blockDim.x + threadIdx.x;
#pragma unroll
    for (int j = 0; j < 4; j++, idx += stride) {
        int t = idx >> 8;
        int c = (idx & 255) << 2;
        int s0 = g_tok_slot[t][0], s1 = g_tok_slot[t][1];
        float w0 = g_slot_w[s0], w1 = g_slot_w[s1];
        const __half2* a2 = (const __half2*)(g_Y + (size_t)s0 * DIM + c);
        const __half2* b2 = (const __half2*)(g_Y + (size_t)s1 * DIM + c);
        float2 a01 = __half22float2(a2[0]), a23 = __half22float2(a2[1]);
        float2 b01 = __half22float2(b2[0]), b23 = __half22float2(b2[1]);
        float4 o;
        o.x = w0 * a01.x + w1 * b01.x;
        o.y = w0 * a01.y + w1 * b01.y;
        o.z = w0 * a23.x + w1 * b23.x;
        o.w = w0 * a23.y + w1 * b23.y;
        *(float4*)(out + (size_t)t * DIM + c) = o;
    }
}

// ---------------- host ----------------
extern "C" void kernel_launch(void* const* d_in, const int* in_sizes, int n_in,
                              void* d_out, int out_size) {
    const float* x  = (const float*)d_in[0];
    const float* Wr = (const float*)d_in[1];
    const float* br = (const float*)d_in[2];
    const float* W1 = (const float*)d_in[3];
    const float* b1 = (const float*)d_in[4];
    const float* W2 = (const float*)d_in[5];
    const float* b2 = (const float*)d_in[6];
    float* out = (float*)d_out;

    void* pW1f; cudaGetSymbolAddress(&pW1f, g_W1f);
    void* pW2f; cudaGetSymbolAddress(&pW2f, g_W2f);
    void* pXf;  cudaGetSymbolAddress(&pXf,  g_Xf);
    void* pHf;  cudaGetSymbolAddress(&pHf,  g_Hf);

    cudaFuncSetAttribute(gemm_mma_kernel<DIM, HID, 0>, cudaFuncAttributeMaxDynamicSharedMemorySize, GEMM_SMEM);
    cudaFuncSetAttribute(gemm_mma_kernel<HID, DIM, 1>, cudaFuncAttributeMaxDynamicSharedMemorySize, GEMM_SMEM);

    // side streams forked off the capturing (legacy) stream
    cudaStream_t side, side2;
    cudaStreamCreateWithFlags(&side,  cudaStreamNonBlocking);
    cudaStreamCreateWithFlags(&side2, cudaStreamNonBlocking);
    cudaEvent_t evFork, evW1, evW2, evX;
    cudaEventCreateWithFlags(&evFork, cudaEventDisableTiming);
    cudaEventCreateWithFlags(&evW1,   cudaEventDisableTiming);
    cudaEventCreateWithFlags(&evW2,   cudaEventDisableTiming);
    cudaEventCreateWithFlags(&evX,    cudaEventDisableTiming);

    // n4(W) = 8,388,608 float4s; 8/thread -> 4096 CTAs x 256 exactly
    const int wGrid = (int)((size_t)NE * DIM * HID / 4 / (8 * 256));
    // n4(X) = 1,048,576 float4s; 4/thread -> 1024 CTAs x 256 exactly
    const int xGrid = T_TOK * DIM / 4 / (4 * 256);

    cudaEventRecord(evFork, 0);
    cudaStreamWaitEvent(side,  evFork, 0);
    cudaStreamWaitEvent(side2, evFork, 0);

    // side: weight conversions (W1 overlaps prep, W2 overlaps GEMM1)
    convert_f16_kernel<<<wGrid, 256, 0, side>>>(W1, (__half*)pW1f);
    cudaEventRecord(evW1, side);
    convert_f16_kernel<<<wGrid, 256, 0, side>>>(W2, (__half*)pW2f);
    cudaEventRecord(evW2, side);

    // side2: X conversion (overlaps routing chain)
    convertX_kernel<<<xGrid, 256, 0, side2>>>(x);
    cudaEventRecord(evX, side2);

    // main (capturing) stream: routing chain
    route_kernel<<<T_TOK / 32, 256>>>(x, Wr, br);
    offsets_kernel<<<1, 1024>>>();
    scatter_kernel<<<T_TOK / 256, 256>>>();

    cudaStreamWaitEvent(0, evW1, 0);
    cudaStreamWaitEvent(0, evX, 0);
    dim3 g1(MTILES, HID / BN);   // 72 x 32
    gemm_mma_kernel<DIM, HID, 0><<<g1, 256, GEMM_SMEM>>>((const __half*)pXf, (const __half*)pW1f, b1);

    cudaStreamWaitEvent(0, evW2, 0);
    dim3 g2(MTILES, DIM / BN);   // 72 x 8
    gemm_mma_kernel<HID, DIM, 1><<<g2, 256, GEMM_SMEM>>>((const __half*)pHf, (const __half*)pW2f, b2);

    combine_kernel<<<T_TOK * DIM / 4 / (4 * 256), 256>>>(out);

    cudaEventDestroy(evFork);
    cudaEventDestroy(evW1);
    cudaEventDestroy(evW2);
    cudaEventDestroy(evX);
    cudaStreamDestroy(side);
    cudaStreamDestroy(side2);
}